// round 4
// baseline (speedup 1.0000x reference)
#include <cuda_runtime.h>

#define POOL      7
#define NUM_ROIS  300
#define FH        200
#define FW        200
#define FC        512
#define FC4       (FC / 4)     // 128 float4 per pixel
#define NITEMS    (NUM_ROIS * POOL * POOL)   // 14700 work items

#define NBLOCKS   1184          // 8 persistent blocks per SM (148 SMs)

// Persistent blocks, 128 threads (thread t owns float4 channel-slot t).
// Item loop with 1-deep software pipeline: while blending/storing item i,
// the 4 corner loads of item i+NBLOCKS are already in flight.
__global__ __launch_bounds__(128, 8)
void roi_pool_kernel(const float4* __restrict__ feat,
                     const int*    __restrict__ rois,
                     float4*       __restrict__ out)
{
    const int t      = threadIdx.x;
    const int stride = gridDim.x;

    int item = blockIdx.x;
    if (item >= NITEMS) return;

    // ---- geometry + load issue for an item ----
    auto geom = [&](int it, float& w00, float& w01, float& w10, float& w11,
                    const float4*& p00, const float4*& p01,
                    const float4*& p10, const float4*& p11) {
        const int roi  = it / (POOL * POOL);
        const int cell = it - roi * (POOL * POOL);
        const int py   = cell / POOL;
        const int px   = cell - py * POOL;

        const int x0 = __ldg(&rois[roi * 4 + 0]);
        const int y0 = __ldg(&rois[roi * 4 + 1]);
        const int w  = __ldg(&rois[roi * 4 + 2]);
        const int h  = __ldg(&rois[roi * 4 + 3]);

        const float sy = (float)py * ((float)h / (float)POOL);
        const float sx = (float)px * ((float)w / (float)POOL);
        const int y_lo = (int)floorf(sy);
        const int x_lo = (int)floorf(sx);
        const int y_hi = min(y_lo + 1, h - 1);
        const int x_hi = min(x_lo + 1, w - 1);
        const float fy = sy - (float)y_lo;
        const float fx = sx - (float)x_lo;
        const float gy = 1.0f - fy;
        const float gx = 1.0f - fx;
        w00 = gy * gx;  w01 = gy * fx;  w10 = fy * gx;  w11 = fy * fx;

        p00 = feat + ((size_t)(y0 + y_lo) * FW + (x0 + x_lo)) * FC4 + t;
        p01 = feat + ((size_t)(y0 + y_lo) * FW + (x0 + x_hi)) * FC4 + t;
        p10 = feat + ((size_t)(y0 + y_hi) * FW + (x0 + x_lo)) * FC4 + t;
        p11 = feat + ((size_t)(y0 + y_hi) * FW + (x0 + x_hi)) * FC4 + t;
    };

    // Prime the pipeline with the first item
    float aw00, aw01, aw10, aw11;
    const float4 *ap00, *ap01, *ap10, *ap11;
    geom(item, aw00, aw01, aw10, aw11, ap00, ap01, ap10, ap11);
    float4 a00 = *ap00, a01 = *ap01, a10 = *ap10, a11 = *ap11;
    int cur = item;

    while (true) {
        const int nxt = cur + stride;

        float bw00, bw01, bw10, bw11;
        float4 b00, b01, b10, b11;
        const bool more = (nxt < NITEMS);
        if (more) {
            const float4 *bp00, *bp01, *bp10, *bp11;
            geom(nxt, bw00, bw01, bw10, bw11, bp00, bp01, bp10, bp11);
            b00 = *bp00; b01 = *bp01; b10 = *bp10; b11 = *bp11;  // in flight
        }

        // Blend + store current item (loads for nxt already outstanding)
        float4 r;
        r.x = aw00 * a00.x + aw01 * a01.x + aw10 * a10.x + aw11 * a11.x;
        r.y = aw00 * a00.y + aw01 * a01.y + aw10 * a10.y + aw11 * a11.y;
        r.z = aw00 * a00.z + aw01 * a01.z + aw10 * a10.z + aw11 * a11.z;
        r.w = aw00 * a00.w + aw01 * a01.w + aw10 * a10.w + aw11 * a11.w;
        out[(size_t)cur * FC4 + t] = r;

        if (!more) break;
        a00 = b00; a01 = b01; a10 = b10; a11 = b11;
        aw00 = bw00; aw01 = bw01; aw10 = bw10; aw11 = bw11;
        cur = nxt;
    }
}

extern "C" void kernel_launch(void* const* d_in, const int* in_sizes, int n_in,
                              void* d_out, int out_size)
{
    const float4* feat = (const float4*)d_in[0];   // (1,200,200,512) f32
    const int*    rois = (const int*)d_in[1];      // (1,300,4) i32
    float4*       out  = (float4*)d_out;           // (1,300,7,7,512) f32

    roi_pool_kernel<<<NBLOCKS, 128>>>(feat, rois, out);
}